// round 1
// baseline (speedup 1.0000x reference)
#include <cuda_runtime.h>

#define N_FULL 50000
#define NLAT 10
#define MU 32
#define BATCH 8
#define TILE 16
#define THREADS 256

// Scratch (allocation-free rule: __device__ globals)
__device__ float  g_encoded[BATCH * NLAT];
__device__ float4 g_dect[N_FULL * 4];   // [node][4 x float4] : 10 decoder vals + pad, 64B rows

// ---------------------------------------------------------------------------
// Kernel 1: encoded[b,i] = x[b,:] . enc_w[i,:] + enc_b[i]   (80 block dots)
// ---------------------------------------------------------------------------
__global__ void encode_kernel(const float* __restrict__ x,
                              const float* __restrict__ ew,
                              const float* __restrict__ eb) {
    int bi = blockIdx.x;            // 0..79
    int b = bi / NLAT, i = bi % NLAT;
    const float4* xv = (const float4*)(x + (size_t)b * N_FULL);
    const float4* wv = (const float4*)(ew + (size_t)i * N_FULL);
    float s = 0.f;
    for (int t = threadIdx.x; t < N_FULL / 4; t += blockDim.x) {
        float4 a = xv[t], w4 = wv[t];
        s = fmaf(a.x, w4.x, s);
        s = fmaf(a.y, w4.y, s);
        s = fmaf(a.z, w4.z, s);
        s = fmaf(a.w, w4.w, s);
    }
    // reduce 256 -> 1
    __shared__ float red[8];
    #pragma unroll
    for (int o = 16; o; o >>= 1) s += __shfl_down_sync(0xffffffffu, s, o);
    if ((threadIdx.x & 31) == 0) red[threadIdx.x >> 5] = s;
    __syncthreads();
    if (threadIdx.x < 8) {
        s = red[threadIdx.x];
        #pragma unroll
        for (int o = 4; o; o >>= 1) s += __shfl_down_sync(0xffu, s, o);
        if (threadIdx.x == 0) g_encoded[bi] = s + eb[i];
    }
}

// ---------------------------------------------------------------------------
// Kernel 2: transpose decoder [10,N] -> g_dect [N][16] (64B padded rows)
// ---------------------------------------------------------------------------
__global__ void prep_kernel(const float* __restrict__ dec) {
    int j = blockIdx.x * blockDim.x + threadIdx.x;
    if (j >= N_FULL) return;
    float d[NLAT];
    #pragma unroll
    for (int i = 0; i < NLAT; i++) d[i] = dec[(size_t)i * N_FULL + j];
    g_dect[j * 4 + 0] = make_float4(d[0], d[1], d[2], d[3]);
    g_dect[j * 4 + 1] = make_float4(d[4], d[5], d[6], d[7]);
    g_dect[j * 4 + 2] = make_float4(d[8], d[9], 0.f, 0.f);
}

// ---------------------------------------------------------------------------
// Kernel 3: main. Per block: TILE nodes.
//   Phase B: gather decoder rows at neighbours into smem
//   Phase C: prefix sums over m:  P0[m]=sum d,  P2[m]=sum d*m^2
//   Phase D: per (node,b): w=sigmoid(enc.bw), closed-form window via K lookup
// ---------------------------------------------------------------------------
__global__ __launch_bounds__(THREADS)
void main_kernel(const float* __restrict__ bw,
                 const int*  __restrict__ nb,
                 float*      __restrict__ out) {
    __shared__ float enc_s[BATCH * NLAT];
    __shared__ float P0s[TILE * NLAT * 33];   // [pl][i][m], stride 33 kills bank conflicts
    __shared__ float P2s[TILE * NLAT * 33];

    int tid = threadIdx.x;
    int p0  = blockIdx.x * TILE;

    if (tid < BATCH * NLAT) enc_s[tid] = g_encoded[tid];

    // ---- Phase B: gather (raw values parked in P0s) ----
    for (int s = tid; s < TILE * MU; s += THREADS) {
        int m  = s & 31;
        int pl = s >> 5;
        int j  = __ldg(&nb[(size_t)(p0 + pl) * MU + m]);
        float4 a  = g_dect[j * 4 + 0];
        float4 b4 = g_dect[j * 4 + 1];
        float4 c4 = g_dect[j * 4 + 2];
        int base = (pl * NLAT) * 33 + m;
        P0s[base +   0] = a.x;  P0s[base +  33] = a.y;
        P0s[base +  66] = a.z;  P0s[base +  99] = a.w;
        P0s[base + 132] = b4.x; P0s[base + 165] = b4.y;
        P0s[base + 198] = b4.z; P0s[base + 231] = b4.w;
        P0s[base + 264] = c4.x; P0s[base + 297] = c4.y;
    }
    __syncthreads();

    // ---- Phase C: in-place inclusive prefix sums over m ----
    if (tid < TILE * NLAT) {
        int base = tid * 33;
        float s0 = 0.f, s2 = 0.f;
        #pragma unroll
        for (int m = 0; m < MU; m++) {
            float g = P0s[base + m];
            s0 += g;
            s2 = fmaf(g, (float)(m * m), s2);
            P0s[base + m] = s0;
            P2s[base + m] = s2;
        }
    }
    __syncthreads();

    // ---- Phase D: evaluate per (node, b) ----
    if (tid < TILE * BATCH) {
        int b  = tid & 7;
        int pl = tid >> 3;
        int p  = p0 + pl;
        float eb_[NLAT];
        #pragma unroll
        for (int k = 0; k < NLAT; k++) eb_[k] = enc_s[b * NLAT + k];

        float acc = 0.f;
        #pragma unroll
        for (int i = 0; i < NLAT; i++) {
            // w[b,i,p] = sigmoid( sum_k enc[b,k] * bw[i,k,p] )
            float t = 0.f;
            #pragma unroll
            for (int k = 0; k < NLAT; k++)
                t = fmaf(eb_[k], __ldg(&bw[(size_t)(i * NLAT + k) * N_FULL + p]), t);
            float w = 1.f / (1.f + __expf(-t));
            float u = fmaxf(32.f * w, 1e-6f);      // 32*w  (window cutoff)
            float cinv = __fdividef(1.f, u * u);   // c = 1/(32w)^2
            int K = min(MU, (int)u + 1);           // #nonzero window terms (incl. harmless 0)
            float S2K = (float)((K - 1) * K * (2 * K - 1)) * (1.f / 6.f);
            int idx = (pl * NLAT + i) * 33 + (K - 1);
            float P0 = P0s[idx];
            float P2 = P2s[idx];
            float norm = (float)K - cinv * S2K;           // sum of window weights
            float sm = __fdividef(P0 - cinv * P2, norm);  // smoothed[b,i,p]
            acc = fmaf(eb_[i], sm, acc);
        }
        out[(size_t)b * N_FULL + p] = acc;
    }
}

// ---------------------------------------------------------------------------
extern "C" void kernel_launch(void* const* d_in, const int* in_sizes, int n_in,
                              void* d_out, int out_size) {
    const float* x   = (const float*)d_in[0];
    const float* ew  = (const float*)d_in[1];
    const float* ebv = (const float*)d_in[2];
    const float* dec = (const float*)d_in[3];
    const float* bw  = (const float*)d_in[4];
    const int*   nb  = (const int*)d_in[5];
    float* out = (float*)d_out;

    encode_kernel<<<BATCH * NLAT, 256>>>(x, ew, ebv);
    prep_kernel<<<(N_FULL + 255) / 256, 256>>>(dec);
    main_kernel<<<N_FULL / TILE, THREADS>>>(bw, nb, out);
}

// round 2
// speedup vs baseline: 1.0462x; 1.0462x over previous
#include <cuda_runtime.h>

#define N_FULL 50000
#define NLAT 10
#define MU 32
#define BATCH 8
#define TILE 16
#define NVEC 12500          // N_FULL / 4
#define ENC_CHUNKS 25
#define ENC_VPC 500         // float4 per chunk (25*500 = 12500)

// Scratch (allocation-free rule: __device__ globals)
__device__ float  g_encoded[BATCH * NLAT];
__device__ float4 g_dect[N_FULL * 4];   // [node][4 x float4]: 10 decoder vals + pad, 64B rows

// ---------------------------------------------------------------------------
// Kernel 0: seed g_encoded with bias (reset every launch for determinism)
// ---------------------------------------------------------------------------
__global__ void init_kernel(const float* __restrict__ eb) {
    int t = threadIdx.x;
    if (t < BATCH * NLAT) g_encoded[t] = eb[t % NLAT];
}

// ---------------------------------------------------------------------------
// Kernel 1: encoded[b,i] += x[b,chunk] . enc_w[i,chunk]  (split-K, i-tiled)
// grid (ENC_CHUNKS, BATCH), 256 threads
// ---------------------------------------------------------------------------
__global__ __launch_bounds__(256)
void encode_kernel(const float* __restrict__ x,
                   const float* __restrict__ ew) {
    int b  = blockIdx.y;
    int c0 = blockIdx.x * ENC_VPC;
    int tid = threadIdx.x;
    int t0 = tid, t1 = tid + 256;

    const float4* xv = (const float4*)(x + (size_t)b * N_FULL) + c0;
    float4 xa = xv[t0];                                   // t0 < 500 always
    float4 xb = (t1 < ENC_VPC) ? xv[t1] : make_float4(0.f, 0.f, 0.f, 0.f);

    float acc[NLAT];
    #pragma unroll
    for (int i = 0; i < NLAT; i++) {
        const float4* wv = (const float4*)(ew + (size_t)i * N_FULL) + c0;
        float4 wa = wv[t0];
        float4 wb = (t1 < ENC_VPC) ? wv[t1] : make_float4(0.f, 0.f, 0.f, 0.f);
        float s;
        s = xa.x * wa.x;
        s = fmaf(xa.y, wa.y, s);
        s = fmaf(xa.z, wa.z, s);
        s = fmaf(xa.w, wa.w, s);
        s = fmaf(xb.x, wb.x, s);
        s = fmaf(xb.y, wb.y, s);
        s = fmaf(xb.z, wb.z, s);
        s = fmaf(xb.w, wb.w, s);
        acc[i] = s;
    }

    __shared__ float red[8][NLAT];
    #pragma unroll
    for (int i = 0; i < NLAT; i++) {
        float s = acc[i];
        #pragma unroll
        for (int o = 16; o; o >>= 1) s += __shfl_down_sync(0xffffffffu, s, o);
        if ((tid & 31) == 0) red[tid >> 5][i] = s;
    }
    __syncthreads();
    if (tid < NLAT) {
        float s = 0.f;
        #pragma unroll
        for (int w = 0; w < 8; w++) s += red[w][tid];
        atomicAdd(&g_encoded[b * NLAT + tid], s);
    }
}

// ---------------------------------------------------------------------------
// Kernel 2: transpose decoder [10,N] -> g_dect [N][16] (64B padded rows)
// ---------------------------------------------------------------------------
__global__ void prep_kernel(const float* __restrict__ dec) {
    int j = blockIdx.x * blockDim.x + threadIdx.x;
    if (j >= N_FULL) return;
    float d[NLAT];
    #pragma unroll
    for (int i = 0; i < NLAT; i++) d[i] = dec[(size_t)i * N_FULL + j];
    g_dect[j * 4 + 0] = make_float4(d[0], d[1], d[2], d[3]);
    g_dect[j * 4 + 1] = make_float4(d[4], d[5], d[6], d[7]);
    g_dect[j * 4 + 2] = make_float4(d[8], d[9], 0.f, 0.f);
}

// ---------------------------------------------------------------------------
// Kernel 3: main. Per block: TILE=16 nodes, 128 threads.
//   Phase A: stage neighbour indices in smem (coalesced)
//   Phase B: cooperative gather — 3 lanes share one 64B decoder row (1 line)
//   Phase C: prefix sums over m:  P0[m]=sum d,  P2[m]=sum d*m^2
//   Phase D: per (node,b): w=sigmoid(enc.bw), closed-form window via K lookup
// ---------------------------------------------------------------------------
__global__ __launch_bounds__(128)
void main_kernel(const float* __restrict__ bw,
                 const int*  __restrict__ nb,
                 float*      __restrict__ out) {
    __shared__ float enc_s[BATCH * NLAT];
    __shared__ int   nbs[TILE * MU];
    __shared__ float P0s[TILE * NLAT * 33];   // [pl][i][m], stride 33
    __shared__ float P2s[TILE * NLAT * 33];

    int tid = threadIdx.x;
    int p0  = blockIdx.x * TILE;

    if (tid < BATCH * NLAT) enc_s[tid] = g_encoded[tid];

    // ---- Phase A: stage indices ----
    for (int s = tid; s < TILE * MU; s += 128)
        nbs[s] = __ldg(&nb[(size_t)p0 * MU + s]);
    __syncthreads();

    // ---- Phase B: cooperative gather (3 lanes per index -> 1 line) ----
    #pragma unroll
    for (int it = 0; it < TILE * MU * 3 / 128; it++) {
        int t = it * 128 + tid;
        int s = t / 3;                 // index id (0..511)
        int chunk = t - s * 3;         // 0,1,2
        int j = nbs[s];
        float4 v = g_dect[j * 4 + chunk];
        int base = (s >> 5) * (NLAT * 33) + (s & 31) + chunk * 132;
        P0s[base]      = v.x;
        P0s[base + 33] = v.y;
        if (chunk != 2) {
            P0s[base + 66] = v.z;
            P0s[base + 99] = v.w;
        }
    }
    __syncthreads();

    // ---- Phase C: in-place inclusive prefix sums over m ----
    for (int r = tid; r < TILE * NLAT; r += 128) {
        int base = r * 33;
        float s0 = 0.f, s2 = 0.f;
        #pragma unroll
        for (int m = 0; m < MU; m++) {
            float g = P0s[base + m];
            s0 += g;
            s2 = fmaf(g, (float)(m * m), s2);
            P0s[base + m] = s0;
            P2s[base + m] = s2;
        }
    }
    __syncthreads();

    // ---- Phase D: evaluate per (node, b); 128 threads = 16 nodes x 8 b ----
    {
        int b  = tid & 7;
        int pl = tid >> 3;
        int p  = p0 + pl;
        float eb_[NLAT];
        #pragma unroll
        for (int k = 0; k < NLAT; k++) eb_[k] = enc_s[b * NLAT + k];

        float acc = 0.f;
        #pragma unroll
        for (int i = 0; i < NLAT; i++) {
            float t = 0.f;
            #pragma unroll
            for (int k = 0; k < NLAT; k++)
                t = fmaf(eb_[k], __ldg(&bw[(size_t)(i * NLAT + k) * N_FULL + p]), t);
            float w = 1.f / (1.f + __expf(-t));
            float u = fmaxf(32.f * w, 1e-6f);      // 32*w (window cutoff)
            float cinv = __fdividef(1.f, u * u);   // 1/(32w)^2
            int K = min(MU, (int)u + 1);           // #window terms
            float S2K = (float)((K - 1) * K * (2 * K - 1)) * (1.f / 6.f);
            int idx = (pl * NLAT + i) * 33 + (K - 1);
            float P0 = P0s[idx];
            float P2 = P2s[idx];
            float norm = (float)K - cinv * S2K;
            float sm = __fdividef(P0 - cinv * P2, norm);
            acc = fmaf(eb_[i], sm, acc);
        }
        out[(size_t)b * N_FULL + p] = acc;
    }
}

// ---------------------------------------------------------------------------
extern "C" void kernel_launch(void* const* d_in, const int* in_sizes, int n_in,
                              void* d_out, int out_size) {
    const float* x   = (const float*)d_in[0];
    const float* ew  = (const float*)d_in[1];
    const float* ebv = (const float*)d_in[2];
    const float* dec = (const float*)d_in[3];
    const float* bw  = (const float*)d_in[4];
    const int*   nb  = (const int*)d_in[5];
    float* out = (float*)d_out;

    init_kernel<<<1, 128>>>(ebv);
    encode_kernel<<<dim3(ENC_CHUNKS, BATCH), 256>>>(x, ew);
    prep_kernel<<<(N_FULL + 255) / 256, 256>>>(dec);
    main_kernel<<<N_FULL / TILE, 128>>>(bw, nb, out);
}

// round 4
// speedup vs baseline: 1.3066x; 1.2489x over previous
#include <cuda_runtime.h>

#define N_FULL 50000
#define NLAT 10
#define MU 32
#define BATCH 8
#define TILE 16
#define ENC_CHUNKS 25
#define ENC_VPC 500         // float4 per chunk (25*500 = 12500 = N/4)
#define ENC_BLOCKS (ENC_CHUNKS * BATCH)     // 200
#define PREP_BLOCKS ((N_FULL + 255) / 256)  // 196

// Scratch (allocation-free rule: __device__ globals)
__device__ float  g_encoded[BATCH * NLAT];
__device__ float4 g_dect[N_FULL * 4];   // [node][4 x float4]: 10 decoder vals + pad, 64B rows

// ---------------------------------------------------------------------------
// Kernel 0: seed g_encoded with bias (reset every launch for determinism)
// ---------------------------------------------------------------------------
__global__ void init_kernel(const float* __restrict__ eb) {
    int t = threadIdx.x;
    if (t < BATCH * NLAT) g_encoded[t] = eb[t % NLAT];
}

// ---------------------------------------------------------------------------
// Kernel 1 (fused): blocks [0,200) encode split-K; blocks [200,396) transpose
// decoder into g_dect.
// ---------------------------------------------------------------------------
__global__ __launch_bounds__(256)
void encprep_kernel(const float* __restrict__ x,
                    const float* __restrict__ ew,
                    const float* __restrict__ dec) {
    int bid = blockIdx.x;
    int tid = threadIdx.x;

    if (bid < ENC_BLOCKS) {
        // ---- encode: encoded[b,i] += x[b,chunk] . enc_w[i,chunk] ----
        int b  = bid / ENC_CHUNKS;
        int c0 = (bid % ENC_CHUNKS) * ENC_VPC;
        int t0 = tid, t1 = tid + 256;

        const float4* xv = (const float4*)(x + (size_t)b * N_FULL) + c0;
        float4 xa = xv[t0];
        float4 xb = (t1 < ENC_VPC) ? xv[t1] : make_float4(0.f, 0.f, 0.f, 0.f);

        float acc[NLAT];
        #pragma unroll
        for (int i = 0; i < NLAT; i++) {
            const float4* wv = (const float4*)(ew + (size_t)i * N_FULL) + c0;
            float4 wa = wv[t0];
            float4 wb = (t1 < ENC_VPC) ? wv[t1] : make_float4(0.f, 0.f, 0.f, 0.f);
            float s;
            s = xa.x * wa.x;
            s = fmaf(xa.y, wa.y, s);
            s = fmaf(xa.z, wa.z, s);
            s = fmaf(xa.w, wa.w, s);
            s = fmaf(xb.x, wb.x, s);
            s = fmaf(xb.y, wb.y, s);
            s = fmaf(xb.z, wb.z, s);
            s = fmaf(xb.w, wb.w, s);
            acc[i] = s;
        }

        __shared__ float red[8][NLAT];
        #pragma unroll
        for (int i = 0; i < NLAT; i++) {
            float s = acc[i];
            #pragma unroll
            for (int o = 16; o; o >>= 1) s += __shfl_down_sync(0xffffffffu, s, o);
            if ((tid & 31) == 0) red[tid >> 5][i] = s;
        }
        __syncthreads();
        if (tid < NLAT) {
            float s = 0.f;
            #pragma unroll
            for (int w = 0; w < 8; w++) s += red[w][tid];
            atomicAdd(&g_encoded[b * NLAT + tid], s);
        }
    } else {
        // ---- prep: transpose decoder [10,N] -> g_dect [N][16] ----
        int j = (bid - ENC_BLOCKS) * 256 + tid;
        if (j >= N_FULL) return;
        float d[NLAT];
        #pragma unroll
        for (int i = 0; i < NLAT; i++) d[i] = dec[(size_t)i * N_FULL + j];
        g_dect[j * 4 + 0] = make_float4(d[0], d[1], d[2], d[3]);
        g_dect[j * 4 + 1] = make_float4(d[4], d[5], d[6], d[7]);
        g_dect[j * 4 + 2] = make_float4(d[8], d[9], 0.f, 0.f);
    }
}

// ---------------------------------------------------------------------------
// Kernel 2: main. Per block: TILE=16 nodes, 256 threads.
//   A: stage neighbour indices (coalesced) — 512 entries, 2 per thread
//   B: cooperative gather — 3 lanes share one 64B decoder row (1 L1 line)
//   C: prefix sums over m:  P0[m]=sum d,  P2[m]=sum d*m^2   (160 rows)
//   D: per (node,b,i-half): closed-form window via K lookup; halves combined
// ---------------------------------------------------------------------------
__global__ __launch_bounds__(256)
void main_kernel(const float* __restrict__ bw,
                 const int*  __restrict__ nb,
                 float*      __restrict__ out) {
    __shared__ float enc_s[BATCH * NLAT];
    __shared__ int   nbs[TILE * MU];          // 2KB; reused as float[256] for D-reduce
    __shared__ float P0s[TILE * NLAT * 33];   // [pl][i][m], stride 33
    __shared__ float P2s[TILE * NLAT * 33];

    int tid = threadIdx.x;
    int p0  = blockIdx.x * TILE;

    if (tid < BATCH * NLAT) enc_s[tid] = g_encoded[tid];

    // ---- Phase A: stage indices (512 = 2 per thread) ----
    nbs[tid]       = __ldg(&nb[(size_t)p0 * MU + tid]);
    nbs[tid + 256] = __ldg(&nb[(size_t)p0 * MU + tid + 256]);
    __syncthreads();

    // ---- Phase B: cooperative gather (3 lanes per index -> 1 line) ----
    #pragma unroll
    for (int it = 0; it < TILE * MU * 3 / 256; it++) {
        int t = it * 256 + tid;
        int s = t / 3;                 // index id (0..511)
        int chunk = t - s * 3;         // 0,1,2
        int j = nbs[s];
        float4 v = g_dect[j * 4 + chunk];
        int base = (s >> 5) * (NLAT * 33) + (s & 31) + chunk * 132;
        P0s[base]      = v.x;
        P0s[base + 33] = v.y;
        if (chunk != 2) {
            P0s[base + 66] = v.z;
            P0s[base + 99] = v.w;
        }
    }
    __syncthreads();

    // ---- Phase C: in-place inclusive prefix sums over m (160 rows) ----
    if (tid < TILE * NLAT) {
        int base = tid * 33;
        float s0 = 0.f, s2 = 0.f;
        #pragma unroll
        for (int m = 0; m < MU; m++) {
            float g = P0s[base + m];
            s0 += g;
            s2 = fmaf(g, (float)(m * m), s2);
            P0s[base + m] = s0;
            P2s[base + m] = s2;
        }
    }
    __syncthreads();

    // ---- Phase D: 256 threads = 16 nodes x 8 b x 2 i-halves ----
    float* redf = (float*)nbs;
    {
        int b    = tid & 7;
        int pl   = (tid >> 3) & 15;
        int half = tid >> 7;
        int p    = p0 + pl;
        float eb_[NLAT];
        #pragma unroll
        for (int k = 0; k < NLAT; k++) eb_[k] = enc_s[b * NLAT + k];

        const float* bwp = bw + (size_t)half * 5 * NLAT * N_FULL + p;
        float acc = 0.f;
        #pragma unroll
        for (int ii = 0; ii < 5; ii++) {
            int i = half * 5 + ii;
            float t = 0.f;
            #pragma unroll
            for (int k = 0; k < NLAT; k++)
                t = fmaf(eb_[k], __ldg(&bwp[(size_t)(ii * NLAT + k) * N_FULL]), t);
            float w = 1.f / (1.f + __expf(-t));
            float u = fmaxf(32.f * w, 1e-6f);      // 32*w (window cutoff)
            float cinv = __fdividef(1.f, u * u);   // 1/(32w)^2
            int K = min(MU, (int)u + 1);           // #window terms
            float S2K = (float)((K - 1) * K * (2 * K - 1)) * (1.f / 6.f);
            int idx = (pl * NLAT + i) * 33 + (K - 1);
            float P0 = P0s[idx];
            float P2 = P2s[idx];
            float norm = (float)K - cinv * S2K;
            float sm = __fdividef(P0 - cinv * P2, norm);
            acc = fmaf(eb_[i], sm, acc);
        }
        redf[tid] = acc;
    }
    __syncthreads();
    if (tid < 128) {
        int b  = tid & 7;
        int pl = tid >> 3;
        out[(size_t)b * N_FULL + p0 + pl] = redf[tid] + redf[tid + 128];
    }
}

// ---------------------------------------------------------------------------
extern "C" void kernel_launch(void* const* d_in, const int* in_sizes, int n_in,
                              void* d_out, int out_size) {
    const float* x   = (const float*)d_in[0];
    const float* ew  = (const float*)d_in[1];
    const float* ebv = (const float*)d_in[2];
    const float* dec = (const float*)d_in[3];
    const float* bw  = (const float*)d_in[4];
    const int*   nb  = (const int*)d_in[5];
    float* out = (float*)d_out;

    init_kernel<<<1, 128>>>(ebv);
    encprep_kernel<<<ENC_BLOCKS + PREP_BLOCKS, 256>>>(x, ew, dec);
    main_kernel<<<N_FULL / TILE, 256>>>(bw, nb, out);
}